// round 16
// baseline (speedup 1.0000x reference)
#include <cuda_runtime.h>
#include <cstdint>

#define D_MODEL 1024
#define HALF    32
#define T_LEN   8192
#define BATCH   4
#define ROWS    (BATCH * T_LEN)   // 32768
#define TAPS    32
#define TT      64
#define RSTR    20   // u32 stride: 16 data + 4 pad (conflict-free)

// scratch: projected modes xp[row][n] fp32 (4 MB)
__device__ float g_xp[ROWS * HALF];
// conv output: 16 fp16x2 pairs per row (2 MB)
__device__ uint32_t g_y[ROWS * 16];

// ---------------------------------------------------------------------------
// pack helpers
// ---------------------------------------------------------------------------
__device__ __forceinline__ uint32_t pack_h2(float f0, float f1) {
    uint32_t d;
    asm("cvt.rn.f16x2.f32 %0, %1, %2;" : "=r"(d) : "f"(f1), "f"(f0));
    return d;
}
__device__ __forceinline__ void mma_f16(float& c0, float& c1, float& c2, float& c3,
                                        uint32_t a0, uint32_t a1, uint32_t a2, uint32_t a3,
                                        uint32_t b0, uint32_t b1) {
    asm volatile(
        "mma.sync.aligned.m16n8k16.row.col.f32.f16.f16.f32 "
        "{%0,%1,%2,%3}, {%4,%5,%6,%7}, {%8,%9}, {%0,%1,%2,%3};"
        : "+f"(c0), "+f"(c1), "+f"(c2), "+f"(c3)
        : "r"(a0), "r"(a1), "r"(a2), "r"(a3), "r"(b0), "r"(b1));
}

// ===========================================================================
// K1: xp[row][n] = sum_d x[row][d]*W_in[n][d]
// SINGLE-TERM fp16 mma; smem double-buffered; register pipeline DEPTH 2.
// (R15, unchanged — proven 29.4 us)
// ===========================================================================
#define K1_A_U32 (128 * RSTR)             // 2560
#define K1_B_U32 (32 * RSTR)              // 640
#define K1_STAGE (K1_A_U32 + K1_B_U32)    // 3200 u32
#define K1_SMEM_BYTES (2 * K1_STAGE * 4)  // 25.6 KB

__global__ void __launch_bounds__(256) proj_mma_kernel(const float* __restrict__ x,
                                                       const float* __restrict__ W_in)
{
    extern __shared__ uint32_t sm1[];
    const int tid = threadIdx.x;
    const int wid = tid >> 5;
    const int lid = tid & 31;
    const int g   = lid >> 2;
    const int tig = lid & 3;
    const int row0 = blockIdx.x * 128;

    const int mroww = (wid & 3) * 32;
    const int ncolw = (wid >> 2) * 16;

    float4 paA[4], paB[4];
    float4 pbA, pbB;

    auto ldg_chunk = [&](int c, float4 (&pa)[4], float4& pb) {
#pragma unroll
        for (int p = 0; p < 4; p++) {
            const int f = tid + p * 256;
            pa[p] = *(const float4*)(x + (size_t)(row0 + (f >> 3)) * D_MODEL +
                                     c * 32 + (f & 7) * 4);
        }
        pb = *(const float4*)(W_in + (size_t)(tid >> 3) * D_MODEL + c * 32 + (tid & 7) * 4);
    };
    auto sts_chunk = [&](int buf, float4 (&pa)[4], float4& pb) {
        uint32_t* AB = sm1 + buf * K1_STAGE;
        uint32_t* BB = AB + K1_A_U32;
#pragma unroll
        for (int p = 0; p < 4; p++) {
            const int f = tid + p * 256;
            const int r = f >> 3, q = f & 7;
            *(uint2*)&AB[r * RSTR + q * 2] =
                make_uint2(pack_h2(pa[p].x, pa[p].y), pack_h2(pa[p].z, pa[p].w));
        }
        const int n = tid >> 3, q = tid & 7;
        *(uint2*)&BB[n * RSTR + q * 2] =
            make_uint2(pack_h2(pb.x, pb.y), pack_h2(pb.z, pb.w));
    };

    float acc[2][2][4];
#pragma unroll
    for (int mt = 0; mt < 2; mt++)
#pragma unroll
        for (int nt = 0; nt < 2; nt++)
#pragma unroll
            for (int i = 0; i < 4; i++) acc[mt][nt][i] = 0.f;

    auto compute = [&](int c) {
        const uint32_t* AB = sm1 + (c & 1) * K1_STAGE;
        const uint32_t* BB = AB + K1_A_U32;
#pragma unroll
        for (int ks = 0; ks < 2; ks++) {
            const int e0 = ks * 8 + tig;
            uint32_t ah[2][4];
#pragma unroll
            for (int mt = 0; mt < 2; mt++) {
                const int r = mroww + mt * 16 + g;
                ah[mt][0] = AB[r * RSTR + e0];
                ah[mt][1] = AB[(r + 8) * RSTR + e0];
                ah[mt][2] = AB[r * RSTR + e0 + 4];
                ah[mt][3] = AB[(r + 8) * RSTR + e0 + 4];
            }
            uint32_t bh_[2][2];
#pragma unroll
            for (int nt = 0; nt < 2; nt++) {
                const int n = ncolw + nt * 8 + g;
                bh_[nt][0] = BB[n * RSTR + e0];
                bh_[nt][1] = BB[n * RSTR + e0 + 4];
            }
#pragma unroll
            for (int mt = 0; mt < 2; mt++)
#pragma unroll
                for (int nt = 0; nt < 2; nt++) {
                    float* cc = acc[mt][nt];
                    mma_f16(cc[0], cc[1], cc[2], cc[3],
                            ah[mt][0], ah[mt][1], ah[mt][2], ah[mt][3],
                            bh_[nt][0], bh_[nt][1]);
                }
        }
    };

    ldg_chunk(0, paA, pbA);
    ldg_chunk(1, paB, pbB);
    sts_chunk(0, paA, pbA);
    ldg_chunk(2, paA, pbA);
    __syncthreads();

#pragma unroll 1
    for (int c = 0; c < 32; c += 2) {
        {
            sts_chunk((c + 1) & 1, paB, pbB);
            if (c + 3 < 32) ldg_chunk(c + 3, paB, pbB);
            compute(c);
            __syncthreads();
        }
        {
            if (c + 2 < 32) sts_chunk((c + 2) & 1, paA, pbA);
            if (c + 4 < 32) ldg_chunk(c + 4, paA, pbA);
            compute(c + 1);
            __syncthreads();
        }
    }

#pragma unroll
    for (int mt = 0; mt < 2; mt++) {
        const int r0 = row0 + mroww + mt * 16 + g;
#pragma unroll
        for (int nt = 0; nt < 2; nt++) {
            const int col = ncolw + nt * 8 + tig * 2;
            *(float2*)(g_xp + (size_t)r0 * HALF + col) =
                make_float2(acc[mt][nt][0], acc[mt][nt][1]);
            *(float2*)(g_xp + (size_t)(r0 + 8) * HALF + col) =
                make_float2(acc[mt][nt][2], acc[mt][nt][3]);
        }
    }
}

// ===========================================================================
// K2: FIR taps + causal conv; writes y as fp16x2 pairs  (R13, unchanged)
// ===========================================================================
__global__ void __launch_bounds__(256) conv_kernel(
    const float* __restrict__ log_tau, const float* __restrict__ freq,
    const float* __restrict__ Bp,      const float* __restrict__ Cp,
    const float* __restrict__ log_dt)
{
    __shared__ float xp_s[(TT + TAPS - 1) * 32];   // 95 rows
    __shared__ float kk[TAPS][32];
    __shared__ float y_s[TT][32];
    __shared__ float pg[32], pl[32], pa[32];

    const int tid = threadIdx.x;
    const int blk = blockIdx.x;
    const int b   = blk >> 7;
    const int t0  = (blk & 127) * TT;

    if (tid < 32) {
        float dt  = expf(log_dt[0]);
        float tau = fmaxf(expf(log_tau[tid]), 1e-4f);
        pl[tid] = -tau * dt;
        pa[tid] = freq[tid] * dt;
        pg[tid] = logf(fabsf(Bp[tid]) + 1e-9f) + logf(fabsf(Cp[tid]) + 1e-9f);
    }

    for (int idx = tid; idx < (TT + TAPS - 1) * 32; idx += 256) {
        const int j = idx >> 5, n = idx & 31;
        const int tq = t0 - (TAPS - 1) + j;
        xp_s[idx] = (tq >= 0) ? g_xp[((size_t)b * T_LEN + tq) * HALF + n] : 0.f;
    }
    __syncthreads();

    for (int idx = tid; idx < TAPS * 32; idx += 256) {
        const int s = idx >> 5, n = idx & 31;
        kk[s][n] = expf(pg[n] + (float)s * pl[n]) * cosf((float)s * pa[n]);
    }
    __syncthreads();

    {
        const int n  = tid & 31;
        const int tg = tid >> 5;
#pragma unroll
        for (int r = 0; r < 8; r++) {
            const int tl = tg * 8 + r;
            float acc = 0.f;
            const float* base = &xp_s[(tl + TAPS - 1) * 32 + n];
#pragma unroll
            for (int s = 0; s < TAPS; s++) {
                acc += kk[s][n] * base[-s * 32];
            }
            y_s[tl][n] = acc;
        }
    }
    __syncthreads();

    for (int idx = tid; idx < TT * 16; idx += 256) {
        const int t = idx >> 4, kp = idx & 15;
        g_y[((size_t)b * T_LEN + t0 + t) * 16 + kp] =
            pack_h2(y_s[t][2 * kp], y_s[t][2 * kp + 1]);
    }
}

// ===========================================================================
// K3: GEMM2  out[t][d] = sum_n y[t][n] * W_out[d][n]
// SINGLE-TERM fp16 mma. 4 t-tiles per CTA, all A loads hoisted to prologue.
// grid (64, 4) = 256 CTAs -> single wave. B staged once per CTA.
// ===========================================================================
#define K3_A_U32      (128 * RSTR)           // 2560 per buffer
#define K3_B_U32      (256 * RSTR)           // 5120
#define K3_SMEM_BYTES ((2 * K3_A_U32 + K3_B_U32) * 4)   // 41 KB

__global__ void __launch_bounds__(256) gemm2_kernel(const float* __restrict__ W_out,
                                                    float* __restrict__ out)
{
    extern __shared__ uint32_t sm3[];
    uint32_t* Abuf = sm3;                      // 2 x 2560
    uint32_t* Bs   = sm3 + 2 * K3_A_U32;

    const int tid = threadIdx.x;
    const int wid = tid >> 5;
    const int lid = tid & 31;
    const int g   = lid >> 2;
    const int tig = lid & 3;

    const int tbase = blockIdx.x * 512;        // 4 tiles of 128
    const int d0    = blockIdx.y * 256;

    // ---- prologue: ALL A loads in flight immediately (8 LDG.128/thr) ----
    uint4 pa[4][2];
    const int ar = (tid & 127) >> 0;           // placeholder to keep indices clear
#pragma unroll
    for (int j = 0; j < 4; j++) {
#pragma unroll
        for (int p = 0; p < 2; p++) {
            const int f = tid + p * 256;
            const int r = f >> 2, q4 = f & 3;
            pa[j][p] = *(const uint4*)&g_y[(size_t)(tbase + j * 128 + r) * 16 + q4 * 4];
        }
    }
    (void)ar;

    // ---- stage B once ----
#pragma unroll
    for (int p = 0; p < 8; p++) {
        const int f = tid + p * 256;
        const int r = f >> 3, q = f & 7;
        float4 v = *(const float4*)(W_out + (size_t)(d0 + r) * HALF + q * 4);
        *(uint2*)&Bs[r * RSTR + q * 2] =
            make_uint2(pack_h2(v.x, v.y), pack_h2(v.z, v.w));
    }

    const int mg = wid & 3;
    const int dg = wid >> 2;

#pragma unroll 1
    for (int j = 0; j < 4; j++) {
        // stage A tile j
        uint32_t* As = Abuf + (j & 1) * K3_A_U32;
#pragma unroll
        for (int p = 0; p < 2; p++) {
            const int f = tid + p * 256;
            const int r = f >> 2, q4 = f & 3;
            *(uint4*)&As[r * RSTR + q4 * 4] = pa[j][p];
        }
        __syncthreads();

        // A fragments for this tile
        uint32_t af[2][2][4];
#pragma unroll
        for (int mt = 0; mt < 2; mt++) {
            const int r = mg * 32 + mt * 16 + g;
#pragma unroll
            for (int ks = 0; ks < 2; ks++) {
                const int e0 = ks * 8 + tig;
                af[mt][ks][0] = As[r * RSTR + e0];
                af[mt][ks][1] = As[(r + 8) * RSTR + e0];
                af[mt][ks][2] = As[r * RSTR + e0 + 4];
                af[mt][ks][3] = As[(r + 8) * RSTR + e0 + 4];
            }
        }

        const int t0 = tbase + j * 128;
#pragma unroll 1
        for (int ch = 0; ch < 16; ch++) {
            const int nb = dg * 128 + ch * 8;
            float acc[2][4];
#pragma unroll
            for (int mt = 0; mt < 2; mt++)
#pragma unroll
                for (int i = 0; i < 4; i++) acc[mt][i] = 0.f;

#pragma unroll
            for (int ks = 0; ks < 2; ks++) {
                const int e0 = ks * 8 + tig;
                const int nr = nb + g;
                uint32_t b0 = Bs[nr * RSTR + e0];
                uint32_t b1 = Bs[nr * RSTR + e0 + 4];
#pragma unroll
                for (int mt = 0; mt < 2; mt++) {
                    float* cc = acc[mt];
                    mma_f16(cc[0], cc[1], cc[2], cc[3],
                            af[mt][ks][0], af[mt][ks][1], af[mt][ks][2], af[mt][ks][3],
                            b0, b1);
                }
            }

            const int col = d0 + nb + tig * 2;
#pragma unroll
            for (int mt = 0; mt < 2; mt++) {
                const int tr = t0 + mg * 32 + mt * 16 + g;
                *(float2*)(out + (size_t)tr * D_MODEL + col) =
                    make_float2(acc[mt][0], acc[mt][1]);
                *(float2*)(out + (size_t)(tr + 8) * D_MODEL + col) =
                    make_float2(acc[mt][2], acc[mt][3]);
            }
        }
        __syncthreads();
    }
}

// ---------------------------------------------------------------------------
extern "C" void kernel_launch(void* const* d_in, const int* in_sizes, int n_in,
                              void* d_out, int out_size)
{
    const float* x       = (const float*)d_in[0];
    const float* log_tau = (const float*)d_in[1];
    const float* freq    = (const float*)d_in[2];
    const float* Bp      = (const float*)d_in[3];
    const float* Cp      = (const float*)d_in[4];
    const float* log_dt  = (const float*)d_in[5];
    const float* W_in    = (const float*)d_in[6];
    const float* W_out   = (const float*)d_in[7];
    float* out           = (float*)d_out;

    (void)in_sizes; (void)n_in; (void)out_size;

    static bool attr_set = false;
    if (!attr_set) {
        cudaFuncSetAttribute(proj_mma_kernel,
                             cudaFuncAttributeMaxDynamicSharedMemorySize, K1_SMEM_BYTES);
        cudaFuncSetAttribute(gemm2_kernel,
                             cudaFuncAttributeMaxDynamicSharedMemorySize, K3_SMEM_BYTES);
        attr_set = true;
    }

    proj_mma_kernel<<<ROWS / 128, 256, K1_SMEM_BYTES>>>(x, W_in);
    conv_kernel<<<(BATCH * T_LEN) / TT, 256>>>(log_tau, freq, Bp, Cp, log_dt);
    gemm2_kernel<<<dim3(ROWS / 512, D_MODEL / 256), 256, K3_SMEM_BYTES>>>(W_out, out);
}

// round 17
// speedup vs baseline: 1.0312x; 1.0312x over previous
#include <cuda_runtime.h>
#include <cstdint>

#define D_MODEL 1024
#define HALF    32
#define T_LEN   8192
#define BATCH   4
#define ROWS    (BATCH * T_LEN)   // 32768
#define TAPS    32
#define TT      64
#define RSTR    20   // u32 stride: 16 data + 4 pad (conflict-free)

// scratch: projected modes xp[row][n] fp32 (4 MB)
__device__ float g_xp[ROWS * HALF];
// conv output: 16 fp16x2 pairs per row (2 MB)
__device__ uint32_t g_y[ROWS * 16];
// precomputed FIR taps kk[s][n] (4 KB), written by K1 block 0
__device__ float g_kk[TAPS * 32];

// ---------------------------------------------------------------------------
// pack helpers
// ---------------------------------------------------------------------------
__device__ __forceinline__ uint32_t pack_h2(float f0, float f1) {
    uint32_t d;
    asm("cvt.rn.f16x2.f32 %0, %1, %2;" : "=r"(d) : "f"(f1), "f"(f0));
    return d;
}
__device__ __forceinline__ void mma_f16(float& c0, float& c1, float& c2, float& c3,
                                        uint32_t a0, uint32_t a1, uint32_t a2, uint32_t a3,
                                        uint32_t b0, uint32_t b1) {
    asm volatile(
        "mma.sync.aligned.m16n8k16.row.col.f32.f16.f16.f32 "
        "{%0,%1,%2,%3}, {%4,%5,%6,%7}, {%8,%9}, {%0,%1,%2,%3};"
        : "+f"(c0), "+f"(c1), "+f"(c2), "+f"(c3)
        : "r"(a0), "r"(a1), "r"(a2), "r"(a3), "r"(b0), "r"(b1));
}

// ===========================================================================
// K1: xp[row][n] = sum_d x[row][d]*W_in[n][d]
// SINGLE-TERM fp16 mma; smem double-buffered; register pipeline DEPTH 2.
// Block 0 warp 0 additionally computes the FIR taps -> g_kk (hidden).
// ===========================================================================
#define K1_A_U32 (128 * RSTR)             // 2560
#define K1_B_U32 (32 * RSTR)              // 640
#define K1_STAGE (K1_A_U32 + K1_B_U32)    // 3200 u32
#define K1_SMEM_BYTES (2 * K1_STAGE * 4)  // 25.6 KB

__global__ void __launch_bounds__(256) proj_mma_kernel(
    const float* __restrict__ x,       const float* __restrict__ W_in,
    const float* __restrict__ log_tau, const float* __restrict__ freq,
    const float* __restrict__ Bp,      const float* __restrict__ Cp,
    const float* __restrict__ log_dt)
{
    extern __shared__ uint32_t sm1[];
    const int tid = threadIdx.x;
    const int wid = tid >> 5;
    const int lid = tid & 31;
    const int g   = lid >> 2;
    const int tig = lid & 3;
    const int row0 = blockIdx.x * 128;

    // ---- one warp on the whole grid computes the taps (runs concurrently) ----
    if (blockIdx.x == 0 && wid == 0) {
        const int n = lid;
        float dt  = expf(log_dt[0]);
        float tau = fmaxf(expf(log_tau[n]), 1e-4f);
        float pl  = -tau * dt;
        float pan = freq[n] * dt;
        float pgv = logf(fabsf(Bp[n]) + 1e-9f) + logf(fabsf(Cp[n]) + 1e-9f);
#pragma unroll 1
        for (int s = 0; s < TAPS; s++) {
            g_kk[s * 32 + n] = expf(pgv + (float)s * pl) * cosf((float)s * pan);
        }
    }

    const int mroww = (wid & 3) * 32;
    const int ncolw = (wid >> 2) * 16;

    float4 paA[4], paB[4];
    float4 pbA, pbB;

    auto ldg_chunk = [&](int c, float4 (&pa)[4], float4& pb) {
#pragma unroll
        for (int p = 0; p < 4; p++) {
            const int f = tid + p * 256;
            pa[p] = *(const float4*)(x + (size_t)(row0 + (f >> 3)) * D_MODEL +
                                     c * 32 + (f & 7) * 4);
        }
        pb = *(const float4*)(W_in + (size_t)(tid >> 3) * D_MODEL + c * 32 + (tid & 7) * 4);
    };
    auto sts_chunk = [&](int buf, float4 (&pa)[4], float4& pb) {
        uint32_t* AB = sm1 + buf * K1_STAGE;
        uint32_t* BB = AB + K1_A_U32;
#pragma unroll
        for (int p = 0; p < 4; p++) {
            const int f = tid + p * 256;
            const int r = f >> 3, q = f & 7;
            *(uint2*)&AB[r * RSTR + q * 2] =
                make_uint2(pack_h2(pa[p].x, pa[p].y), pack_h2(pa[p].z, pa[p].w));
        }
        const int n = tid >> 3, q = tid & 7;
        *(uint2*)&BB[n * RSTR + q * 2] =
            make_uint2(pack_h2(pb.x, pb.y), pack_h2(pb.z, pb.w));
    };

    float acc[2][2][4];
#pragma unroll
    for (int mt = 0; mt < 2; mt++)
#pragma unroll
        for (int nt = 0; nt < 2; nt++)
#pragma unroll
            for (int i = 0; i < 4; i++) acc[mt][nt][i] = 0.f;

    auto compute = [&](int c) {
        const uint32_t* AB = sm1 + (c & 1) * K1_STAGE;
        const uint32_t* BB = AB + K1_A_U32;
#pragma unroll
        for (int ks = 0; ks < 2; ks++) {
            const int e0 = ks * 8 + tig;
            uint32_t ah[2][4];
#pragma unroll
            for (int mt = 0; mt < 2; mt++) {
                const int r = mroww + mt * 16 + g;
                ah[mt][0] = AB[r * RSTR + e0];
                ah[mt][1] = AB[(r + 8) * RSTR + e0];
                ah[mt][2] = AB[r * RSTR + e0 + 4];
                ah[mt][3] = AB[(r + 8) * RSTR + e0 + 4];
            }
            uint32_t bh_[2][2];
#pragma unroll
            for (int nt = 0; nt < 2; nt++) {
                const int n = ncolw + nt * 8 + g;
                bh_[nt][0] = BB[n * RSTR + e0];
                bh_[nt][1] = BB[n * RSTR + e0 + 4];
            }
#pragma unroll
            for (int mt = 0; mt < 2; mt++)
#pragma unroll
                for (int nt = 0; nt < 2; nt++) {
                    float* cc = acc[mt][nt];
                    mma_f16(cc[0], cc[1], cc[2], cc[3],
                            ah[mt][0], ah[mt][1], ah[mt][2], ah[mt][3],
                            bh_[nt][0], bh_[nt][1]);
                }
        }
    };

    ldg_chunk(0, paA, pbA);
    ldg_chunk(1, paB, pbB);
    sts_chunk(0, paA, pbA);
    ldg_chunk(2, paA, pbA);
    __syncthreads();

#pragma unroll 1
    for (int c = 0; c < 32; c += 2) {
        {
            sts_chunk((c + 1) & 1, paB, pbB);
            if (c + 3 < 32) ldg_chunk(c + 3, paB, pbB);
            compute(c);
            __syncthreads();
        }
        {
            if (c + 2 < 32) sts_chunk((c + 2) & 1, paA, pbA);
            if (c + 4 < 32) ldg_chunk(c + 4, paA, pbA);
            compute(c + 1);
            __syncthreads();
        }
    }

#pragma unroll
    for (int mt = 0; mt < 2; mt++) {
        const int r0 = row0 + mroww + mt * 16 + g;
#pragma unroll
        for (int nt = 0; nt < 2; nt++) {
            const int col = ncolw + nt * 8 + tig * 2;
            *(float2*)(g_xp + (size_t)r0 * HALF + col) =
                make_float2(acc[mt][nt][0], acc[mt][nt][1]);
            *(float2*)(g_xp + (size_t)(r0 + 8) * HALF + col) =
                make_float2(acc[mt][nt][2], acc[mt][nt][3]);
        }
    }
}

// ===========================================================================
// K2: causal conv using precomputed taps (no transcendentals)
// ===========================================================================
__global__ void __launch_bounds__(256) conv_kernel()
{
    __shared__ float xp_s[(TT + TAPS - 1) * 32];   // 95 rows
    __shared__ float kk[TAPS * 32];
    __shared__ float y_s[TT][32];

    const int tid = threadIdx.x;
    const int blk = blockIdx.x;
    const int b   = blk >> 7;
    const int t0  = (blk & 127) * TT;

    // load taps (4 KB, L2-hot)
    for (int idx = tid; idx < TAPS * 32; idx += 256) {
        kk[idx] = g_kk[idx];
    }

    for (int idx = tid; idx < (TT + TAPS - 1) * 32; idx += 256) {
        const int j = idx >> 5, n = idx & 31;
        const int tq = t0 - (TAPS - 1) + j;
        xp_s[idx] = (tq >= 0) ? g_xp[((size_t)b * T_LEN + tq) * HALF + n] : 0.f;
    }
    __syncthreads();

    {
        const int n  = tid & 31;
        const int tg = tid >> 5;
#pragma unroll
        for (int r = 0; r < 8; r++) {
            const int tl = tg * 8 + r;
            float acc = 0.f;
            const float* base = &xp_s[(tl + TAPS - 1) * 32 + n];
#pragma unroll
            for (int s = 0; s < TAPS; s++) {
                acc += kk[s * 32 + n] * base[-s * 32];
            }
            y_s[tl][n] = acc;
        }
    }
    __syncthreads();

    for (int idx = tid; idx < TT * 16; idx += 256) {
        const int t = idx >> 4, kp = idx & 15;
        g_y[((size_t)b * T_LEN + t0 + t) * 16 + kp] =
            pack_h2(y_s[t][2 * kp], y_s[t][2 * kp + 1]);
    }
}

// ===========================================================================
// K3: GEMM2  out[t][d] = sum_n y[t][n] * W_out[d][n]
// SINGLE-TERM fp16 mma. CTA 128 t x 256 d, grid (256, 4).  (R15-proven)
// ===========================================================================
#define K3_A_U32      (128 * RSTR)           // 2560
#define K3_B_U32      (256 * RSTR)           // 5120
#define K3_SMEM_BYTES ((K3_A_U32 + K3_B_U32) * 4)   // 30720

__global__ void __launch_bounds__(256) gemm2_kernel(const float* __restrict__ W_out,
                                                    float* __restrict__ out)
{
    extern __shared__ uint32_t sm3[];
    uint32_t* As = sm3;
    uint32_t* Bs = sm3 + K3_A_U32;

    const int tid = threadIdx.x;
    const int wid = tid >> 5;
    const int lid = tid & 31;
    const int g   = lid >> 2;
    const int tig = lid & 3;

    const int t0 = blockIdx.x * 128;
    const int d0 = blockIdx.y * 256;

#pragma unroll
    for (int p = 0; p < 2; p++) {
        const int f = tid + p * 256;
        const int r = f >> 2, j = f & 3;
        uint4 v = *(const uint4*)&g_y[(size_t)(t0 + r) * 16 + j * 4];
        *(uint4*)&As[r * RSTR + j * 4] = v;
    }
#pragma unroll
    for (int p = 0; p < 8; p++) {
        const int f = tid + p * 256;
        const int r = f >> 3, q = f & 7;
        float4 v = *(const float4*)(W_out + (size_t)(d0 + r) * HALF + q * 4);
        *(uint2*)&Bs[r * RSTR + q * 2] =
            make_uint2(pack_h2(v.x, v.y), pack_h2(v.z, v.w));
    }
    __syncthreads();

    const int mg = wid & 3;
    const int dg = wid >> 2;

    uint32_t af[2][2][4];
#pragma unroll
    for (int mt = 0; mt < 2; mt++) {
        const int r = mg * 32 + mt * 16 + g;
#pragma unroll
        for (int ks = 0; ks < 2; ks++) {
            const int e0 = ks * 8 + tig;
            af[mt][ks][0] = As[r * RSTR + e0];
            af[mt][ks][1] = As[(r + 8) * RSTR + e0];
            af[mt][ks][2] = As[r * RSTR + e0 + 4];
            af[mt][ks][3] = As[(r + 8) * RSTR + e0 + 4];
        }
    }

#pragma unroll 1
    for (int ch = 0; ch < 16; ch++) {
        const int nb = dg * 128 + ch * 8;
        float acc[2][4];
#pragma unroll
        for (int mt = 0; mt < 2; mt++)
#pragma unroll
            for (int i = 0; i < 4; i++) acc[mt][i] = 0.f;

#pragma unroll
        for (int ks = 0; ks < 2; ks++) {
            const int e0 = ks * 8 + tig;
            const int nr = nb + g;
            uint32_t b0 = Bs[nr * RSTR + e0];
            uint32_t b1 = Bs[nr * RSTR + e0 + 4];
#pragma unroll
            for (int mt = 0; mt < 2; mt++) {
                float* cc = acc[mt];
                mma_f16(cc[0], cc[1], cc[2], cc[3],
                        af[mt][ks][0], af[mt][ks][1], af[mt][ks][2], af[mt][ks][3],
                        b0, b1);
            }
        }

        const int col = d0 + nb + tig * 2;
#pragma unroll
        for (int mt = 0; mt < 2; mt++) {
            const int tr = t0 + mg * 32 + mt * 16 + g;
            *(float2*)(out + (size_t)tr * D_MODEL + col) =
                make_float2(acc[mt][0], acc[mt][1]);
            *(float2*)(out + (size_t)(tr + 8) * D_MODEL + col) =
                make_float2(acc[mt][2], acc[mt][3]);
        }
    }
}

// ---------------------------------------------------------------------------
extern "C" void kernel_launch(void* const* d_in, const int* in_sizes, int n_in,
                              void* d_out, int out_size)
{
    const float* x       = (const float*)d_in[0];
    const float* log_tau = (const float*)d_in[1];
    const float* freq    = (const float*)d_in[2];
    const float* Bp      = (const float*)d_in[3];
    const float* Cp      = (const float*)d_in[4];
    const float* log_dt  = (const float*)d_in[5];
    const float* W_in    = (const float*)d_in[6];
    const float* W_out   = (const float*)d_in[7];
    float* out           = (float*)d_out;

    (void)in_sizes; (void)n_in; (void)out_size;

    static bool attr_set = false;
    if (!attr_set) {
        cudaFuncSetAttribute(proj_mma_kernel,
                             cudaFuncAttributeMaxDynamicSharedMemorySize, K1_SMEM_BYTES);
        cudaFuncSetAttribute(gemm2_kernel,
                             cudaFuncAttributeMaxDynamicSharedMemorySize, K3_SMEM_BYTES);
        attr_set = true;
    }

    proj_mma_kernel<<<ROWS / 128, 256, K1_SMEM_BYTES>>>(x, W_in, log_tau, freq,
                                                        Bp, Cp, log_dt);
    conv_kernel<<<(BATCH * T_LEN) / TT, 256>>>();
    gemm2_kernel<<<dim3(ROWS / 128, D_MODEL / 256), 256, K3_SMEM_BYTES>>>(W_out, out);
}